// round 17
// baseline (speedup 1.0000x reference)
#include <cuda_runtime.h>
#include <cuda_fp16.h>
#include <cstdint>

// ===========================================================================
// Problem: B=32, T=128, F=1024, CONV_UNITS=2048, SHORT_UNITS=2048, RATE=4
//   out[b, 0:2016,    :] = memory[b, 32:2048,   :]
//   out[b, 2016:2048, :] = compression (GEMM)
//   out[b, 2048:3968, :] = memory[b, 2176:4096, :]
//   out[b, 3968:4096, :] = inputs[b, :, :]
// GEMM: C(1024x1024) = A(1024x4096) @ W(4096x1024) + bias
//   A row m=(b*32+t): 4096 contiguous floats at memory + b*2^22 + 2097152 + t*4096
//
// fp16 m16n8k16 + ldmatrix, 16-warp GEMM (R15). This round: W kept in its
// ORIGINAL k-major layout as fp16 (g_Wh); B fragments via ldmatrix.x4.trans.
// The W smem-transpose in the convert kernel is deleted -> convert is pure
// streaming (no smem, no syncs, MLP-4 loads, STG.128 stores).
// ===========================================================================

#define CP_ASYNC16(dst, src) \
    asm volatile("cp.async.cg.shared.global [%0], [%1], 16;" \
                 :: "r"(dst), "l"(src) : "memory")
#define CP_ASYNC_COMMIT() asm volatile("cp.async.commit_group;" ::: "memory")
#define CP_ASYNC_WAIT2()  asm volatile("cp.async.wait_group 2;" ::: "memory")
#define CP_ASYNC_WAIT0()  asm volatile("cp.async.wait_group 0;" ::: "memory")

__device__ __forceinline__ uint32_t smem_u32(const void* p) {
    uint32_t a;
    asm("{ .reg .u64 t; cvta.to.shared.u64 t, %1; cvt.u32.u64 %0, t; }"
        : "=r"(a) : "l"(p));
    return a;
}

__device__ __forceinline__ void ldmatrix_x4(uint32_t& r0, uint32_t& r1,
                                            uint32_t& r2, uint32_t& r3,
                                            uint32_t addr) {
    asm volatile("ldmatrix.sync.aligned.m8n8.x4.shared.b16 {%0,%1,%2,%3}, [%4];"
                 : "=r"(r0), "=r"(r1), "=r"(r2), "=r"(r3) : "r"(addr));
}

__device__ __forceinline__ void ldmatrix_x4_trans(uint32_t& r0, uint32_t& r1,
                                                  uint32_t& r2, uint32_t& r3,
                                                  uint32_t addr) {
    asm volatile("ldmatrix.sync.aligned.m8n8.x4.trans.shared.b16 "
                 "{%0,%1,%2,%3}, [%4];"
                 : "=r"(r0), "=r"(r1), "=r"(r2), "=r"(r3) : "r"(addr));
}

__device__ __forceinline__ void mma_f16_16n8k16(float* c, const uint32_t* a,
                                                const uint32_t* b) {
    asm volatile(
        "mma.sync.aligned.m16n8k16.row.col.f32.f16.f16.f32 "
        "{%0,%1,%2,%3}, {%4,%5,%6,%7}, {%8,%9}, {%0,%1,%2,%3};"
        : "+f"(c[0]), "+f"(c[1]), "+f"(c[2]), "+f"(c[3])
        : "r"(a[0]), "r"(a[1]), "r"(a[2]), "r"(a[3]),
          "r"(b[0]), "r"(b[1]));
}

__device__ __forceinline__ uint32_t pack_half2(float a, float b) {
    __half2 h = __floats2half2_rn(a, b);
    return *(uint32_t*)&h;
}

// fp16 operand scratch: A (1024 m x 4096 k) and W (4096 k x 1024 n), 8 MB each.
__device__ __half g_Ah[1024 * 4096];
__device__ __half g_Wh[4096 * 1024];

// ---------------------------------------------------------------------------
// Fused convert: PURE STREAMING, no smem, no syncs.
// Blocks 0..1023:    A slices of `memory` -> g_Ah  (gathered rows, k-contig)
// Blocks 1024..2047: W (flat 4M floats)   -> g_Wh  (same layout)
// Each thread: 2 tasks; task = 8 consecutive fp32 (2x float4) -> 1 uint4.
// All 4 loads front-batched -> MLP=4.
// ---------------------------------------------------------------------------
__global__ void convert_all(const float* __restrict__ memory,
                            const float* __restrict__ W)
{
    if (blockIdx.x < 1024) {
        const unsigned pbase = blockIdx.x * 512u + threadIdx.x;   // pair index
        float4 v[4];
#pragma unroll
        for (int rep = 0; rep < 2; rep++) {
            const unsigned p = pbase + rep * 256u;
            const unsigned i0 = p << 3;                 // element idx, mult of 8
            const unsigned m = i0 >> 12;
            const unsigned kq = i0 & 4095u;
            const float* src = memory + ((size_t)(m >> 5) << 22) + 2097152u
                               + ((size_t)(m & 31) << 12) + kq;
            v[2 * rep]     = *(const float4*)src;
            v[2 * rep + 1] = *(const float4*)(src + 4);
        }
#pragma unroll
        for (int rep = 0; rep < 2; rep++) {
            const unsigned p = pbase + rep * 256u;
            const unsigned i0 = p << 3;
            const float4 a = v[2 * rep], b = v[2 * rep + 1];
            uint4 u;
            u.x = pack_half2(a.x, a.y);
            u.y = pack_half2(a.z, a.w);
            u.z = pack_half2(b.x, b.y);
            u.w = pack_half2(b.z, b.w);
            *(uint4*)(g_Ah + i0) = u;
        }
    } else {
        const unsigned pbase = (blockIdx.x - 1024) * 512u + threadIdx.x;
        float4 v[4];
#pragma unroll
        for (int rep = 0; rep < 2; rep++) {
            const unsigned i0 = (pbase + rep * 256u) << 3;
            v[2 * rep]     = *(const float4*)(W + i0);
            v[2 * rep + 1] = *(const float4*)(W + i0 + 4);
        }
#pragma unroll
        for (int rep = 0; rep < 2; rep++) {
            const unsigned i0 = (pbase + rep * 256u) << 3;
            const float4 a = v[2 * rep], b = v[2 * rep + 1];
            uint4 u;
            u.x = pack_half2(a.x, a.y);
            u.y = pack_half2(a.z, a.w);
            u.z = pack_half2(b.x, b.y);
            u.w = pack_half2(b.z, b.w);
            *(uint4*)(g_Wh + i0) = u;
        }
    }
}

// ---------------------------------------------------------------------------
// fp16 GEMM. CTA tile 64x128, K-chunk 64, 4-stage cp.async.
// Grid (8,16) = 128 CTAs, 512 threads / 16 warps.
// Warp map: ws = wid&3 spatial (32x64 tile); kh = wid>>2 per-chunk K-split.
// A smem: 64 rows x 144B (72 halves, pad) -> ldmatrix (non-trans).
// B smem: 64 k-rows x 272B (128 n-halves + pad) -> ldmatrix.trans:
//   lane addr: k-row = kh*16 + (lid&15), n-off = wn + np*16 + ((lid>>4)<<3)
//   {r0,r1,r2,r3} = {bf[2np][0], bf[2np][1], bf[2np+1][0], bf[2np+1][1]}
// ---------------------------------------------------------------------------
#define A_ST 72
#define A_BYTES (64 * 144)                    // 9216
#define B_ROW 272                             // bytes per B k-row (256 + 16)
#define B_BYTES (64 * B_ROW)                  // 17408
#define STAGE_BYTES (A_BYTES + B_BYTES)       // 26624
#define NSTAGE 4
#define NTHREADS 512

__global__ void __launch_bounds__(NTHREADS, 1)
gemm_f16(const float* __restrict__ bias, float* __restrict__ out)
{
    extern __shared__ __align__(16) char smem[];
    const int tid = threadIdx.x;
    const int wid = tid >> 5;
    const int lid = tid & 31;
    const int m0 = blockIdx.y * 64;
    const int n0 = blockIdx.x * 128;
    const int ws = wid & 3;
    const int kh = wid >> 2;            // 0..3
    const int wm = (ws & 1) * 32;
    const int wn = (ws >> 1) * 64;

    // A ldmatrix offsets (halves): same as R15.
    const int klane = ((lid >> 4) << 3) + kh * 16;
    const int a_off0 = (wm + (lid & 15)) * A_ST + klane;
    const int a_off1 = (wm + 16 + (lid & 15)) * A_ST + klane;
    // B ldmatrix.trans byte offsets.
    const int b_krow = kh * 16 + (lid & 15);
    int b_boff[4];
#pragma unroll
    for (int np = 0; np < 4; np++)
        b_boff[np] = b_krow * B_ROW
                     + (wn + np * 16 + ((lid >> 4) << 3)) * 2;

    float acc[2][8][4];
#pragma unroll
    for (int i = 0; i < 2; i++)
#pragma unroll
        for (int j = 0; j < 8; j++)
#pragma unroll
            for (int k = 0; k < 4; k++) acc[i][j][k] = 0.0f;

    auto issue_stage = [&](int kc) {
        const int s = kc % NSTAGE;
        char* sa = smem + s * STAGE_BYTES;
        char* sb = sa + A_BYTES;
        const unsigned k0 = (unsigned)kc << 6;
        // A: 64 rows x 8 x 16B = 512 transfers -> 1 per thread.
        {
            const int r = tid >> 3, q = tid & 7;
            const __half* src = g_Ah + (size_t)(m0 + r) * 4096u + k0 + (q << 3);
            CP_ASYNC16(smem_u32(sa + r * 144 + q * 16), src);
        }
        // B: 64 k-rows x 16 x 16B = 1024 transfers -> 2 per thread.
#pragma unroll
        for (int rep = 0; rep < 2; rep++) {
            const int i = tid + rep * NTHREADS;
            const int r = i >> 4, q = i & 15;
            const __half* src = g_Wh + (size_t)(k0 + r) * 1024u + n0 + (q << 3);
            CP_ASYNC16(smem_u32(sb + r * B_ROW + q * 16), src);
        }
    };

#pragma unroll
    for (int p = 0; p < NSTAGE - 1; ++p) {
        issue_stage(p);
        CP_ASYNC_COMMIT();
    }

    const uint32_t smem_base = smem_u32(smem);

    for (int kc = 0; kc < 64; ++kc) {
        CP_ASYNC_WAIT2();
        __syncthreads();

        if (kc + NSTAGE - 1 < 64) {
            issue_stage(kc + NSTAGE - 1);
            CP_ASYNC_COMMIT();
        }

        const int s = kc % NSTAGE;
        const uint32_t saddr = smem_base + s * STAGE_BYTES;
        const uint32_t baddr = saddr + A_BYTES;

        uint32_t af[2][4], bf[8][2];
        ldmatrix_x4(af[0][0], af[0][1], af[0][2], af[0][3],
                    saddr + (unsigned)a_off0 * 2u);
        ldmatrix_x4(af[1][0], af[1][1], af[1][2], af[1][3],
                    saddr + (unsigned)a_off1 * 2u);
#pragma unroll
        for (int np = 0; np < 4; np++)
            ldmatrix_x4_trans(bf[2 * np][0], bf[2 * np][1],
                              bf[2 * np + 1][0], bf[2 * np + 1][1],
                              baddr + (unsigned)b_boff[np]);
#pragma unroll
        for (int mt = 0; mt < 2; mt++)
#pragma unroll
            for (int nt = 0; nt < 8; nt++)
                mma_f16_16n8k16(acc[mt][nt], af[mt], bf[nt]);
    }
    CP_ASYNC_WAIT0();
    __syncthreads();

    // K-split reduction: kh=1..3 dump partial layers, kh=0 folds.
    float* red = (float*)smem;    // 3 layers x 4 ws x 2048 floats = 96KB
    if (kh != 0) {
#pragma unroll
        for (int mt = 0; mt < 2; mt++)
#pragma unroll
            for (int nt = 0; nt < 8; nt++)
#pragma unroll
                for (int c = 0; c < 4; c++) {
                    const int r = mt * 32 + nt * 4 + c;
                    red[((kh - 1) * 4 + ws) * 2048 + r * 32 + lid] =
                        acc[mt][nt][c];
                }
    }
    __syncthreads();
    if (kh == 0) {
#pragma unroll
        for (int mt = 0; mt < 2; mt++)
#pragma unroll
            for (int nt = 0; nt < 8; nt++)
#pragma unroll
                for (int c = 0; c < 4; c++) {
                    const int r = mt * 32 + nt * 4 + c;
                    const int idx = ws * 2048 + r * 32 + lid;
                    acc[mt][nt][c] += red[idx]
                                    + red[4 * 2048 + idx]
                                    + red[8 * 2048 + idx];
                }

#pragma unroll
        for (int mt = 0; mt < 2; mt++) {
#pragma unroll
            for (int nt = 0; nt < 8; nt++) {
                const int g = n0 + wn + nt * 8 + (lid & 3) * 2;
                const float2 bv = *(const float2*)(bias + g);
                const int m_lo = m0 + wm + mt * 16 + (lid >> 2);
                const int m_hi = m_lo + 8;
                float2 v0 = { acc[mt][nt][0] + bv.x, acc[mt][nt][1] + bv.y };
                float2 v1 = { acc[mt][nt][2] + bv.x, acc[mt][nt][3] + bv.y };
                *(float2*)(out + ((size_t)(m_lo >> 5) << 22)
                               + (size_t)(2016 + (m_lo & 31)) * 1024 + g) = v0;
                *(float2*)(out + ((size_t)(m_hi >> 5) << 22)
                               + (size_t)(2016 + (m_hi & 31)) * 1024 + g) = v1;
            }
        }
    }
}

// ---------------------------------------------------------------------------
// Copy kernel: pure shifted memcpy, float4-vectorized, grid-stride.
// ---------------------------------------------------------------------------
__global__ void copy_kernel(const float4* __restrict__ inputs,
                            const float4* __restrict__ memory,
                            float4* __restrict__ out)
{
    const unsigned total = 32u * 4096u * 256u;
    const unsigned stride = gridDim.x * blockDim.x;
    for (unsigned v = blockIdx.x * blockDim.x + threadIdx.x; v < total; v += stride) {
        unsigned f4 = v & 255u;
        unsigned rg = v >> 8;
        unsigned b  = rg >> 12;
        unsigned r  = rg & 4095u;
        float4 val;
        if (r < 2016u) {
            val = memory[(b << 20) + ((r + 32u) << 8) + f4];
        } else if (r < 2048u) {
            continue;  // compression band written by GEMM kernel
        } else if (r < 3968u) {
            val = memory[(b << 20) + ((r + 128u) << 8) + f4];
        } else {
            val = inputs[(b << 15) + ((r - 3968u) << 8) + f4];
        }
        out[v] = val;
    }
}

// ---------------------------------------------------------------------------
// Launch: convert -> GEMM -> copy (serial).
// ---------------------------------------------------------------------------
extern "C" void kernel_launch(void* const* d_in, const int* in_sizes, int n_in,
                              void* d_out, int out_size)
{
    const float* inputs = (const float*)d_in[0];   // (32, 128, 1024)
    const float* memory = (const float*)d_in[1];   // (32, 4096, 1024)
    const float* conv_w = (const float*)d_in[2];   // (4, 1024, 1024)
    const float* conv_b = (const float*)d_in[3];   // (1024,)
    float* out = (float*)d_out;                    // (32, 4096, 1024)

    cudaFuncSetAttribute(gemm_f16,
                         cudaFuncAttributeMaxDynamicSharedMemorySize,
                         STAGE_BYTES * NSTAGE);

    convert_all<<<2048, 256>>>(memory, conv_w);
    gemm_f16<<<dim3(8, 16), NTHREADS, STAGE_BYTES * NSTAGE>>>(conv_b, out);
    copy_kernel<<<8192, 256>>>((const float4*)inputs, (const float4*)memory,
                               (float4*)out);
}